// round 1
// baseline (speedup 1.0000x reference)
#include <cuda_runtime.h>
#include <math.h>

// ---------------- problem constants ----------------
#define BATCH   8
#define SEQ     4096
#define DM      1024          // d_model
#define NS      256           // state dim
#define M_ROWS  (BATCH*SEQ)   // 32768

#define CHUNK   128
#define NCHUNK  (SEQ/CHUNK)   // 32

// ---------------- scratch (static device globals; no allocation) ----------------
__device__ float g_a[M_ROWS * NS];      // sigmoid gate a   [m, n]
__device__ float g_b[M_ROWS * NS];      // b projection     [m, n]
__device__ float g_h[M_ROWS * NS];      // scan output      [m, n]
__device__ float g_Aagg[BATCH * NCHUNK * NS];
__device__ float g_Bagg[BATCH * NCHUNK * NS];
__device__ float g_carry[BATCH * NCHUNK * NS];

// ---------------- SGEMM tile config ----------------
#define BM 128
#define BN 128
#define BK 8
#define TM 8
#define TN 8
// 256 threads per block, 8x8 microtile per thread

// Accumulate C[m0:m0+128, n0:n0+128] += A[M,K](row-major, lda) * B[N,K]^T (row-major, ldb)
__device__ __forceinline__ void gemm_acc(
    const float* __restrict__ A, const float* __restrict__ B,
    int K, int lda, int ldb,
    int m0, int n0, float acc[TM][TN],
    float (*As)[BM], float (*Bs)[BN])
{
    const int tid = threadIdx.x;
    const int tx  = tid & 15;
    const int ty  = tid >> 4;
    const int lr  = tid >> 1;        // 0..127 row in tile
    const int lk  = (tid & 1) * 4;   // 0 or 4

    const float* Ap = A + (size_t)(m0 + lr) * lda + lk;
    const float* Bp = B + (size_t)(n0 + lr) * ldb + lk;

    float4 av = *(const float4*)Ap;
    float4 bv = *(const float4*)Bp;

    for (int k0 = 0; k0 < K; k0 += BK) {
        As[lk + 0][lr] = av.x; As[lk + 1][lr] = av.y;
        As[lk + 2][lr] = av.z; As[lk + 3][lr] = av.w;
        Bs[lk + 0][lr] = bv.x; Bs[lk + 1][lr] = bv.y;
        Bs[lk + 2][lr] = bv.z; Bs[lk + 3][lr] = bv.w;
        __syncthreads();

        if (k0 + BK < K) {               // register prefetch of next K-slab
            av = *(const float4*)(Ap + k0 + BK);
            bv = *(const float4*)(Bp + k0 + BK);
        }

        #pragma unroll
        for (int k = 0; k < BK; k++) {
            float4 a0 = *(const float4*)&As[k][ty * TM];
            float4 a1 = *(const float4*)&As[k][ty * TM + 4];
            float4 b0 = *(const float4*)&Bs[k][tx * TN];
            float4 b1 = *(const float4*)&Bs[k][tx * TN + 4];
            float ar[TM] = {a0.x, a0.y, a0.z, a0.w, a1.x, a1.y, a1.z, a1.w};
            float br[TN] = {b0.x, b0.y, b0.z, b0.w, b1.x, b1.y, b1.z, b1.w};
            #pragma unroll
            for (int i = 0; i < TM; i++)
                #pragma unroll
                for (int j = 0; j < TN; j++)
                    acc[i][j] += ar[i] * br[j];
        }
        __syncthreads();
    }
}

// ---------------- Phase 1: projections a = sigmoid(xWa^T + ba), b = xB^T ----------------
__global__ __launch_bounds__(256, 2)
void sgemm_proj(const float* __restrict__ X, const float* __restrict__ W,
                const float* __restrict__ bias, int do_sig)
{
    __shared__ float As[BK][BM];
    __shared__ float Bs[BK][BN];
    float acc[TM][TN] = {};

    const int m0 = blockIdx.x * BM;
    const int n0 = blockIdx.y * BN;

    gemm_acc(X, W, DM, DM, DM, m0, n0, acc, As, Bs);

    float* out = do_sig ? g_a : g_b;
    const int tx = threadIdx.x & 15;
    const int ty = threadIdx.x >> 4;

    #pragma unroll
    for (int i = 0; i < TM; i++) {
        const int m = m0 + ty * TM + i;
        #pragma unroll
        for (int j = 0; j < TN; j++) {
            const int n = n0 + tx * TN + j;
            float v = acc[i][j];
            if (do_sig) v = 1.0f / (1.0f + expf(-(v + bias[n])));
            out[(size_t)m * NS + n] = v;
        }
    }
}

// ---------------- Phase 2: chunked linear-recurrence scan ----------------
// h_t = a_t * h_{t-1} + b_t   (h_{-1} = 0), independent per (batch, state)

// 2a: per-chunk aggregates (A = prod a, B = chunk applied to 0)
__global__ void scan_agg()
{
    const int bc = blockIdx.x;               // b*NCHUNK + c
    const int n  = threadIdx.x;
    const int b  = bc / NCHUNK, c = bc % NCHUNK;
    size_t base = ((size_t)b * SEQ + (size_t)c * CHUNK) * NS + n;
    float A = 1.0f, Bv = 0.0f;
    for (int s = 0; s < CHUNK; s++) {
        size_t idx = base + (size_t)s * NS;
        float a  = g_a[idx];
        float bb = g_b[idx];
        A  = a * A;
        Bv = a * Bv + bb;
    }
    g_Aagg[(size_t)bc * NS + n] = A;
    g_Bagg[(size_t)bc * NS + n] = Bv;
}

// 2b: sequential scan over chunk aggregates -> carry-in per chunk
__global__ void scan_carry()
{
    const int b = blockIdx.x;
    const int n = threadIdx.x;
    float h = 0.0f;
    for (int c = 0; c < NCHUNK; c++) {
        size_t idx = ((size_t)b * NCHUNK + c) * NS + n;
        g_carry[idx] = h;
        h = g_Aagg[idx] * h + g_Bagg[idx];
    }
}

// 2c: apply carries, recompute chunk scans, write h
__global__ void scan_apply()
{
    const int bc = blockIdx.x;
    const int n  = threadIdx.x;
    const int b  = bc / NCHUNK, c = bc % NCHUNK;
    float h = g_carry[(size_t)bc * NS + n];
    size_t base = ((size_t)b * SEQ + (size_t)c * CHUNK) * NS + n;
    for (int s = 0; s < CHUNK; s++) {
        size_t idx = base + (size_t)s * NS;
        h = g_a[idx] * h + g_b[idx];
        g_h[idx] = h;
    }
}

// ---------------- Phase 3: y = h C^T + x D^T (fused dual-K GEMM) ----------------
__global__ __launch_bounds__(256, 2)
void sgemm_out(const float* __restrict__ X, const float* __restrict__ Cw,
               const float* __restrict__ Dw, float* __restrict__ Y)
{
    __shared__ float As[BK][BM];
    __shared__ float Bs[BK][BN];
    float acc[TM][TN] = {};

    const int m0 = blockIdx.x * BM;
    const int n0 = blockIdx.y * BN;

    gemm_acc(g_h, Cw, NS, NS, NS, m0, n0, acc, As, Bs);   // h @ C^T  (K=256)
    gemm_acc(X,   Dw, DM, DM, DM, m0, n0, acc, As, Bs);   // x @ D^T  (K=1024)

    const int tx = threadIdx.x & 15;
    const int ty = threadIdx.x >> 4;
    #pragma unroll
    for (int i = 0; i < TM; i++) {
        const int m = m0 + ty * TM + i;
        #pragma unroll
        for (int j = 0; j < TN; j++) {
            const int n = n0 + tx * TN + j;
            Y[(size_t)m * DM + n] = acc[i][j];
        }
    }
}

// ---------------- launch ----------------
extern "C" void kernel_launch(void* const* d_in, const int* in_sizes, int n_in,
                              void* d_out, int out_size)
{
    const float* x    = (const float*)d_in[0];   // [8,4096,1024]
    const float* Wa_w = (const float*)d_in[1];   // [256,1024]
    const float* Wa_b = (const float*)d_in[2];   // [256]
    const float* B_w  = (const float*)d_in[3];   // [256,1024]
    const float* C_w  = (const float*)d_in[4];   // [1024,256]
    const float* D_w  = (const float*)d_in[5];   // [1024,1024]
    float* y = (float*)d_out;                    // [8,4096,1024]

    dim3 blk(256);

    // projections: a (sigmoid + bias) and b
    dim3 gproj(M_ROWS / BM, NS / BN);            // 256 x 2
    sgemm_proj<<<gproj, blk>>>(x, Wa_w, Wa_b, 1);
    sgemm_proj<<<gproj, blk>>>(x, B_w,  Wa_b, 0);

    // chunked scan
    scan_agg  <<<BATCH * NCHUNK, NS>>>();
    scan_carry<<<BATCH, NS>>>();
    scan_apply<<<BATCH * NCHUNK, NS>>>();

    // output projection
    dim3 gout(M_ROWS / BM, DM / BN);             // 256 x 8
    sgemm_out<<<gout, blk>>>(x, C_w, D_w, y);
}

// round 2
// speedup vs baseline: 1.2621x; 1.2621x over previous
#include <cuda_runtime.h>
#include <stdint.h>
#include <math.h>

// ---------------- problem constants ----------------
#define BATCH   8
#define SEQ     4096
#define DM      1024
#define NS      256
#define M_ROWS  (BATCH*SEQ)     // 32768

#define CHUNK   128
#define NCHUNK  (SEQ/CHUNK)     // 32

// ---------------- scratch ----------------
__device__ float g_a[M_ROWS * NS];
__device__ float g_b[M_ROWS * NS];
__device__ float g_h[M_ROWS * NS];
__device__ float g_Aagg[BATCH * NCHUNK * NS];
__device__ float g_Bagg[BATCH * NCHUNK * NS];
__device__ float g_carry[BATCH * NCHUNK * NS];

// ---------------- tf32 mma helpers ----------------
#define PAD 20   // smem row stride in floats (conflict-free fragment loads)

__device__ __forceinline__ uint32_t cvt_tf32(float x) {
    uint32_t r;
    asm("cvt.rna.tf32.f32 %0, %1;" : "=r"(r) : "f"(x));
    return r;
}
__device__ __forceinline__ void split_tf32(float x, uint32_t& hi, uint32_t& lo) {
    hi = cvt_tf32(x);
    lo = cvt_tf32(x - __uint_as_float(hi));
}
__device__ __forceinline__ void mma8(float* c, const uint32_t* a, const uint32_t* b) {
    asm volatile(
        "mma.sync.aligned.m16n8k8.row.col.f32.tf32.tf32.f32 "
        "{%0,%1,%2,%3}, {%4,%5,%6,%7}, {%8,%9}, {%0,%1,%2,%3};"
        : "+f"(c[0]), "+f"(c[1]), "+f"(c[2]), "+f"(c[3])
        : "r"(a[0]), "r"(a[1]), "r"(a[2]), "r"(a[3]), "r"(b[0]), "r"(b[1]));
}

// Accumulate C[m0:+128, n0:+128] += A[M,K] (row-major, lda) * B[N,K]^T (row-major, ldb)
// 256 threads = 8 warps in 2x4 grid; warp tile 64x32; 3xTF32 compensation.
__device__ __forceinline__ void gemm_tiles(
    const float* __restrict__ A, const float* __restrict__ B,
    int K, int lda, int ldb, int m0, int n0,
    float acc[4][4][4], float (*As)[PAD], float (*Bs)[PAD])
{
    const int tid  = threadIdx.x;
    const int warp = tid >> 5, lane = tid & 31;
    const int wr = warp >> 2, wc = warp & 3;      // warp 2x4 grid
    const int gq = lane >> 2, tq = lane & 3;      // quad-pair layout

    for (int k0 = 0; k0 < K; k0 += 16) {
        #pragma unroll
        for (int i = 0; i < 2; i++) {
            int idx = tid + i * 256;
            int row = idx >> 2, c4 = (idx & 3) * 4;
            *(float4*)&As[row][c4] = *(const float4*)(A + (size_t)(m0 + row) * lda + k0 + c4);
            *(float4*)&Bs[row][c4] = *(const float4*)(B + (size_t)(n0 + row) * ldb + k0 + c4);
        }
        __syncthreads();

        #pragma unroll
        for (int ks = 0; ks < 2; ks++) {
            const int kk = ks * 8;
            uint32_t ah[4][4], al[4][4];
            #pragma unroll
            for (int i = 0; i < 4; i++) {
                const int mb = wr * 64 + i * 16;
                split_tf32(As[mb + gq    ][kk + tq    ], ah[i][0], al[i][0]);
                split_tf32(As[mb + gq + 8][kk + tq    ], ah[i][1], al[i][1]);
                split_tf32(As[mb + gq    ][kk + tq + 4], ah[i][2], al[i][2]);
                split_tf32(As[mb + gq + 8][kk + tq + 4], ah[i][3], al[i][3]);
            }
            #pragma unroll
            for (int j = 0; j < 4; j++) {
                const int nb = wc * 32 + j * 8;
                uint32_t bh[2], bl[2];
                split_tf32(Bs[nb + gq][kk + tq    ], bh[0], bl[0]);
                split_tf32(Bs[nb + gq][kk + tq + 4], bh[1], bl[1]);
                #pragma unroll
                for (int i = 0; i < 4; i++) {
                    mma8(acc[i][j], ah[i], bh);   // hi*hi
                    mma8(acc[i][j], al[i], bh);   // lo*hi
                    mma8(acc[i][j], ah[i], bl);   // hi*lo
                }
            }
        }
        __syncthreads();
    }
}

// ---------------- Phase 1: fused projections a = sigmoid(xWa^T+ba), b = xB^T ----------------
__global__ __launch_bounds__(256, 2)
void proj_kernel(const float* __restrict__ X, const float* __restrict__ Wa,
                 const float* __restrict__ bias, const float* __restrict__ Bw)
{
    __shared__ float As[128][PAD];
    __shared__ float Bs[128][PAD];
    float acc[4][4][4] = {};

    const int m0  = blockIdx.x * 128;
    const int n0g = blockIdx.y * 128;          // 0..511 logical (Wa || B)
    const bool is_a = (n0g < NS);
    const float* W  = is_a ? Wa : Bw;
    const int n0    = is_a ? n0g : n0g - NS;

    gemm_tiles(X, W, DM, DM, DM, m0, n0, acc, As, Bs);

    float* out = is_a ? g_a : g_b;
    const int warp = threadIdx.x >> 5, lane = threadIdx.x & 31;
    const int wr = warp >> 2, wc = warp & 3, gq = lane >> 2, tq = lane & 3;

    #pragma unroll
    for (int i = 0; i < 4; i++) {
        #pragma unroll
        for (int j = 0; j < 4; j++) {
            const int row = m0 + wr * 64 + i * 16 + gq;
            const int col = n0 + wc * 32 + j * 8 + tq * 2;
            float v0 = acc[i][j][0], v1 = acc[i][j][1];
            float v2 = acc[i][j][2], v3 = acc[i][j][3];
            if (is_a) {
                float b0 = bias[col], b1 = bias[col + 1];
                v0 = 1.0f / (1.0f + __expf(-(v0 + b0)));
                v1 = 1.0f / (1.0f + __expf(-(v1 + b1)));
                v2 = 1.0f / (1.0f + __expf(-(v2 + b0)));
                v3 = 1.0f / (1.0f + __expf(-(v3 + b1)));
            }
            *(float2*)&out[(size_t)row * NS + col]       = make_float2(v0, v1);
            *(float2*)&out[(size_t)(row + 8) * NS + col] = make_float2(v2, v3);
        }
    }
}

// ---------------- Phase 2: chunked linear-recurrence scan ----------------
__global__ void scan_agg()
{
    const int bc = blockIdx.x;
    const int n  = threadIdx.x;
    const int b  = bc / NCHUNK, c = bc % NCHUNK;
    size_t base = ((size_t)b * SEQ + (size_t)c * CHUNK) * NS + n;
    float A = 1.0f, Bv = 0.0f;
    for (int s = 0; s < CHUNK; s++) {
        size_t idx = base + (size_t)s * NS;
        float a  = g_a[idx];
        float bb = g_b[idx];
        A  = a * A;
        Bv = a * Bv + bb;
    }
    g_Aagg[(size_t)bc * NS + n] = A;
    g_Bagg[(size_t)bc * NS + n] = Bv;
}

__global__ void scan_carry()
{
    const int b = blockIdx.x;
    const int n = threadIdx.x;
    float h = 0.0f;
    for (int c = 0; c < NCHUNK; c++) {
        size_t idx = ((size_t)b * NCHUNK + c) * NS + n;
        g_carry[idx] = h;
        h = g_Aagg[idx] * h + g_Bagg[idx];
    }
}

__global__ void scan_apply()
{
    const int bc = blockIdx.x;
    const int n  = threadIdx.x;
    const int b  = bc / NCHUNK, c = bc % NCHUNK;
    float h = g_carry[(size_t)bc * NS + n];
    size_t base = ((size_t)b * SEQ + (size_t)c * CHUNK) * NS + n;
    for (int s = 0; s < CHUNK; s++) {
        size_t idx = base + (size_t)s * NS;
        h = g_a[idx] * h + g_b[idx];
        g_h[idx] = h;
    }
}

// ---------------- Phase 3: y = h C^T + x D^T ----------------
__global__ __launch_bounds__(256, 2)
void out_kernel(const float* __restrict__ X, const float* __restrict__ Cw,
                const float* __restrict__ Dw, float* __restrict__ Y)
{
    __shared__ float As[128][PAD];
    __shared__ float Bs[128][PAD];
    float acc[4][4][4] = {};

    const int m0 = blockIdx.x * 128;
    const int n0 = blockIdx.y * 128;

    gemm_tiles(g_h, Cw, NS, NS, NS, m0, n0, acc, As, Bs);   // h @ C^T
    gemm_tiles(X,   Dw, DM, DM, DM, m0, n0, acc, As, Bs);   // x @ D^T

    const int warp = threadIdx.x >> 5, lane = threadIdx.x & 31;
    const int wr = warp >> 2, wc = warp & 3, gq = lane >> 2, tq = lane & 3;

    #pragma unroll
    for (int i = 0; i < 4; i++) {
        #pragma unroll
        for (int j = 0; j < 4; j++) {
            const int row = m0 + wr * 64 + i * 16 + gq;
            const int col = n0 + wc * 32 + j * 8 + tq * 2;
            *(float2*)&Y[(size_t)row * DM + col]       = make_float2(acc[i][j][0], acc[i][j][1]);
            *(float2*)&Y[(size_t)(row + 8) * DM + col] = make_float2(acc[i][j][2], acc[i][j][3]);
        }
    }
}

// ---------------- launch ----------------
extern "C" void kernel_launch(void* const* d_in, const int* in_sizes, int n_in,
                              void* d_out, int out_size)
{
    const float* x    = (const float*)d_in[0];
    const float* Wa_w = (const float*)d_in[1];
    const float* Wa_b = (const float*)d_in[2];
    const float* B_w  = (const float*)d_in[3];
    const float* C_w  = (const float*)d_in[4];
    const float* D_w  = (const float*)d_in[5];
    float* y = (float*)d_out;

    dim3 blk(256);

    dim3 gproj(M_ROWS / 128, (2 * NS) / 128);   // 256 x 4
    proj_kernel<<<gproj, blk>>>(x, Wa_w, Wa_b, B_w);

    scan_agg  <<<BATCH * NCHUNK, NS>>>();
    scan_carry<<<BATCH, NS>>>();
    scan_apply<<<BATCH * NCHUNK, NS>>>();

    dim3 gout(M_ROWS / 128, DM / 128);          // 256 x 8
    out_kernel<<<gout, blk>>>(x, C_w, D_w, y);
}

// round 6
// speedup vs baseline: 2.4488x; 1.9403x over previous
#include <cuda_runtime.h>
#include <cuda_bf16.h>
#include <stdint.h>
#include <math.h>

// ---------------- problem constants ----------------
#define BATCH   8
#define SEQ     4096
#define DM      1024
#define NS      256
#define M_ROWS  (BATCH*SEQ)     // 32768
#define CHUNK   128
#define NCHUNK  (SEQ/CHUNK)     // 32

// ---------------- scratch ----------------
__device__ float g_a[M_ROWS * NS];
__device__ float g_b[M_ROWS * NS];
__device__ float g_Aagg[BATCH * NCHUNK * NS];
__device__ float g_Bagg[BATCH * NCHUNK * NS];
__device__ float g_carry[BATCH * NCHUNK * NS];

__device__ __nv_bfloat16 g_xhi[M_ROWS * DM], g_xlo[M_ROWS * DM];
__device__ __nv_bfloat16 g_hhi[M_ROWS * NS], g_hlo[M_ROWS * NS];
__device__ __nv_bfloat16 g_wahi[NS * DM],  g_walo[NS * DM];
__device__ __nv_bfloat16 g_bwhi[NS * DM],  g_bwlo[NS * DM];
__device__ __nv_bfloat16 g_chi[DM * NS],   g_clo[DM * NS];
__device__ __nv_bfloat16 g_dhi[DM * DM],   g_dlo[DM * DM];

// ---------------- GEMM config ----------------
// Block tile 128x128, BK=32 bf16. smem tile: 128 rows x 40 bf16 (pad 8 -> 80B stride,
// ldmatrix conflict-free). 4 tiles per stage (Ahi,Alo,Bhi,Blo), double buffered.
#define LDS_EL  40
#define A_SZ    (128 * LDS_EL * 2)      // 10240 B
#define STAGE   (4 * A_SZ)              // 40960 B
#define SMEM_TOTAL (2 * STAGE)          // 81920 B

// ---------------- PTX helpers ----------------
__device__ __forceinline__ uint32_t smem_u32(const void* p) {
    uint32_t a;
    asm("{ .reg .u64 t; cvta.to.shared.u64 t, %1; cvt.u32.u64 %0, t; }" : "=r"(a) : "l"(p));
    return a;
}
__device__ __forceinline__ void cp16(uint32_t d, const void* s) {
    asm volatile("cp.async.cg.shared.global [%0], [%1], 16;" :: "r"(d), "l"(s));
}
#define CP_COMMIT() asm volatile("cp.async.commit_group;" ::: "memory")
#define CP_WAIT(N)  asm volatile("cp.async.wait_group %0;" :: "n"(N) : "memory")

__device__ __forceinline__ void ldm4(uint32_t* r, uint32_t a) {
    asm volatile("ldmatrix.sync.aligned.m8n8.x4.shared.b16 {%0,%1,%2,%3}, [%4];"
        : "=r"(r[0]), "=r"(r[1]), "=r"(r[2]), "=r"(r[3]) : "r"(a));
}
__device__ __forceinline__ void mma16(float* c, const uint32_t* a, const uint32_t* b) {
    asm volatile("mma.sync.aligned.m16n8k16.row.col.f32.bf16.bf16.f32 "
        "{%0,%1,%2,%3}, {%4,%5,%6,%7}, {%8,%9}, {%0,%1,%2,%3};"
        : "+f"(c[0]), "+f"(c[1]), "+f"(c[2]), "+f"(c[3])
        : "r"(a[0]), "r"(a[1]), "r"(a[2]), "r"(a[3]), "r"(b[0]), "r"(b[1]));
}

// ---------------- per-slab compute: 3-pass bf16 compensation ----------------
__device__ __forceinline__ void compute_slab(uint32_t stg, float acc[4][4][4],
                                             int wr, int wc, int lane)
{
    const uint32_t aoff = ((wr * 64 + (lane & 15)) * LDS_EL + (lane >> 4) * 8) * 2;
    const uint32_t boff = ((wc * 32 + (lane & 15)) * LDS_EL + (lane >> 4) * 8) * 2;
    #pragma unroll
    for (int ks = 0; ks < 2; ks++) {
        const uint32_t kb = ks * 32;   // 16 bf16 = 32 B
        uint32_t ahi[4][4];
        #pragma unroll
        for (int i = 0; i < 4; i++) ldm4(ahi[i], stg + aoff + kb + i * (16 * LDS_EL * 2));

        uint32_t bh[4][2];
        {
            uint32_t t0[4], t1[4];
            ldm4(t0, stg + 2 * A_SZ + boff + kb);
            ldm4(t1, stg + 2 * A_SZ + boff + kb + 16 * LDS_EL * 2);
            bh[0][0] = t0[0]; bh[0][1] = t0[2]; bh[1][0] = t0[1]; bh[1][1] = t0[3];
            bh[2][0] = t1[0]; bh[2][1] = t1[2]; bh[3][0] = t1[1]; bh[3][1] = t1[3];
        }
        #pragma unroll
        for (int j = 0; j < 4; j++)
            #pragma unroll
            for (int i = 0; i < 4; i++) mma16(acc[i][j], ahi[i], bh[j]);   // hi*hi

        {
            uint32_t t0[4], t1[4], bl[4][2];
            ldm4(t0, stg + 3 * A_SZ + boff + kb);
            ldm4(t1, stg + 3 * A_SZ + boff + kb + 16 * LDS_EL * 2);
            bl[0][0] = t0[0]; bl[0][1] = t0[2]; bl[1][0] = t0[1]; bl[1][1] = t0[3];
            bl[2][0] = t1[0]; bl[2][1] = t1[2]; bl[3][0] = t1[1]; bl[3][1] = t1[3];
            #pragma unroll
            for (int j = 0; j < 4; j++)
                #pragma unroll
                for (int i = 0; i < 4; i++) mma16(acc[i][j], ahi[i], bl[j]); // hi*lo
        }
        {
            uint32_t alo[4][4];
            #pragma unroll
            for (int i = 0; i < 4; i++) ldm4(alo[i], stg + A_SZ + aoff + kb + i * (16 * LDS_EL * 2));
            #pragma unroll
            for (int j = 0; j < 4; j++)
                #pragma unroll
                for (int i = 0; i < 4; i++) mma16(acc[i][j], alo[i], bh[j]); // lo*hi
        }
    }
}

// ---------------- pipelined GEMM segment ----------------
__device__ __forceinline__ void gemm_pipe(
    const __nv_bfloat16* __restrict__ Ah, const __nv_bfloat16* __restrict__ Al, int lda, int m0,
    const __nv_bfloat16* __restrict__ Bh, const __nv_bfloat16* __restrict__ Bl, int ldb, int n0,
    int K, uint32_t sb, float acc[4][4][4])
{
    const int tid = threadIdx.x;
    const int warp = tid >> 5, lane = tid & 31;
    const int wr = warp >> 2, wc = warp & 3;

    const __nv_bfloat16* src0 = Ah + (size_t)m0 * lda;
    const __nv_bfloat16* src1 = Al + (size_t)m0 * lda;
    const __nv_bfloat16* src2 = Bh + (size_t)n0 * ldb;
    const __nv_bfloat16* src3 = Bl + (size_t)n0 * ldb;

    auto issue = [&](int slab, int buf) {
        const int k0 = slab * 32;
        const uint32_t db = sb + buf * STAGE;
        #pragma unroll
        for (int t = 0; t < 8; t++) {
            int id   = tid + t * 256;
            int tile = id >> 9;            // 512 16B-chunks per tile
            int c    = id & 511;
            int row  = c >> 2, seg = c & 3;
            const __nv_bfloat16* s;
            if      (tile == 0) s = src0 + (size_t)row * lda + k0 + seg * 8;
            else if (tile == 1) s = src1 + (size_t)row * lda + k0 + seg * 8;
            else if (tile == 2) s = src2 + (size_t)row * ldb + k0 + seg * 8;
            else                s = src3 + (size_t)row * ldb + k0 + seg * 8;
            cp16(db + tile * A_SZ + (row * LDS_EL + seg * 8) * 2, s);
        }
        CP_COMMIT();
    };

    const int nslab = K / 32;
    issue(0, 0);
    for (int s = 0; s < nslab; s++) {
        if (s + 1 < nslab) { issue(s + 1, (s + 1) & 1); CP_WAIT(1); }
        else               { CP_WAIT(0); }
        __syncthreads();
        compute_slab(sb + (s & 1) * STAGE, acc, wr, wc, lane);
        __syncthreads();
    }
}

// ---------------- kernels ----------------
__global__ void split_kernel(const float* __restrict__ src,
                             __nv_bfloat16* __restrict__ hi,
                             __nv_bfloat16* __restrict__ lo, int n)
{
    int i = (blockIdx.x * blockDim.x + threadIdx.x) * 4;
    if (i >= n) return;
    float4 v = *(const float4*)(src + i);
    __nv_bfloat16 h[4], l[4];
    h[0] = __float2bfloat16(v.x); l[0] = __float2bfloat16(v.x - __bfloat162float(h[0]));
    h[1] = __float2bfloat16(v.y); l[1] = __float2bfloat16(v.y - __bfloat162float(h[1]));
    h[2] = __float2bfloat16(v.z); l[2] = __float2bfloat16(v.z - __bfloat162float(h[2]));
    h[3] = __float2bfloat16(v.w); l[3] = __float2bfloat16(v.w - __bfloat162float(h[3]));
    *(uint2*)(hi + i) = *(uint2*)h;
    *(uint2*)(lo + i) = *(uint2*)l;
}

__global__ __launch_bounds__(256, 2)
void proj_kernel(const float* __restrict__ bias)
{
    extern __shared__ char smem[];
    uint32_t sb = smem_u32(smem);
    float acc[4][4][4] = {};

    const int m0 = blockIdx.x * 128;
    const int by = blockIdx.y;               // 0,1 -> a; 2,3 -> b
    const bool is_a = (by < 2);
    const int n0 = (by & 1) * 128;
    const __nv_bfloat16* Wh = is_a ? g_wahi : g_bwhi;
    const __nv_bfloat16* Wl = is_a ? g_walo : g_bwlo;

    gemm_pipe(g_xhi, g_xlo, DM, m0, Wh, Wl, DM, n0, DM, sb, acc);

    float* dst = is_a ? g_a : g_b;
    const int warp = threadIdx.x >> 5, lane = threadIdx.x & 31;
    const int wr = warp >> 2, wc = warp & 3;
    const int gq = lane >> 2, tq = lane & 3;

    #pragma unroll
    for (int i = 0; i < 4; i++) {
        #pragma unroll
        for (int j = 0; j < 4; j++) {
            const int row = m0 + wr * 64 + i * 16 + gq;
            const int col = n0 + wc * 32 + j * 8 + tq * 2;
            float v0 = acc[i][j][0], v1 = acc[i][j][1];
            float v2 = acc[i][j][2], v3 = acc[i][j][3];
            if (is_a) {
                float b0 = bias[col], b1 = bias[col + 1];
                v0 = 1.0f / (1.0f + __expf(-(v0 + b0)));
                v1 = 1.0f / (1.0f + __expf(-(v1 + b1)));
                v2 = 1.0f / (1.0f + __expf(-(v2 + b0)));
                v3 = 1.0f / (1.0f + __expf(-(v3 + b1)));
            }
            *(float2*)&dst[(size_t)row * NS + col]       = make_float2(v0, v1);
            *(float2*)&dst[(size_t)(row + 8) * NS + col] = make_float2(v2, v3);
        }
    }
}

__global__ __launch_bounds__(256, 2)
void out_kernel(float* __restrict__ Y)
{
    extern __shared__ char smem[];
    uint32_t sb = smem_u32(smem);
    float acc[4][4][4] = {};

    const int m0 = blockIdx.x * 128;
    const int n0 = blockIdx.y * 128;

    gemm_pipe(g_hhi, g_hlo, NS, m0, g_chi, g_clo, NS, n0, NS, sb, acc); // h @ C^T
    gemm_pipe(g_xhi, g_xlo, DM, m0, g_dhi, g_dlo, DM, n0, DM, sb, acc); // x @ D^T

    const int warp = threadIdx.x >> 5, lane = threadIdx.x & 31;
    const int wr = warp >> 2, wc = warp & 3;
    const int gq = lane >> 2, tq = lane & 3;

    #pragma unroll
    for (int i = 0; i < 4; i++) {
        #pragma unroll
        for (int j = 0; j < 4; j++) {
            const int row = m0 + wr * 64 + i * 16 + gq;
            const int col = n0 + wc * 32 + j * 8 + tq * 2;
            *(float2*)&Y[(size_t)row * DM + col]       = make_float2(acc[i][j][0], acc[i][j][1]);
            *(float2*)&Y[(size_t)(row + 8) * DM + col] = make_float2(acc[i][j][2], acc[i][j][3]);
        }
    }
}

// ---------------- scan ----------------
__global__ void scan_agg()
{
    const int bc = blockIdx.x, n = threadIdx.x;
    const int b = bc / NCHUNK, c = bc % NCHUNK;
    size_t base = ((size_t)b * SEQ + (size_t)c * CHUNK) * NS + n;
    float A = 1.0f, Bv = 0.0f;
    for (int s = 0; s < CHUNK; s++) {
        size_t idx = base + (size_t)s * NS;
        float a = g_a[idx], bb = g_b[idx];
        A = a * A; Bv = a * Bv + bb;
    }
    g_Aagg[(size_t)bc * NS + n] = A;
    g_Bagg[(size_t)bc * NS + n] = Bv;
}

__global__ void scan_carry()
{
    const int b = blockIdx.x, n = threadIdx.x;
    float h = 0.0f;
    for (int c = 0; c < NCHUNK; c++) {
        size_t idx = ((size_t)b * NCHUNK + c) * NS + n;
        g_carry[idx] = h;
        h = g_Aagg[idx] * h + g_Bagg[idx];
    }
}

__global__ void scan_apply()
{
    const int bc = blockIdx.x, n = threadIdx.x;
    const int b = bc / NCHUNK, c = bc % NCHUNK;
    float h = g_carry[(size_t)bc * NS + n];
    size_t base = ((size_t)b * SEQ + (size_t)c * CHUNK) * NS + n;
    for (int s = 0; s < CHUNK; s++) {
        size_t idx = base + (size_t)s * NS;
        h = g_a[idx] * h + g_b[idx];
        __nv_bfloat16 hh = __float2bfloat16(h);
        g_hhi[idx] = hh;
        g_hlo[idx] = __float2bfloat16(h - __bfloat162float(hh));
    }
}

// ---------------- launch ----------------
extern "C" void kernel_launch(void* const* d_in, const int* in_sizes, int n_in,
                              void* d_out, int out_size)
{
    const float* x    = (const float*)d_in[0];
    const float* Wa_w = (const float*)d_in[1];
    const float* Wa_b = (const float*)d_in[2];
    const float* B_w  = (const float*)d_in[3];
    const float* C_w  = (const float*)d_in[4];
    const float* D_w  = (const float*)d_in[5];
    float* y = (float*)d_out;

    cudaFuncSetAttribute(proj_kernel, cudaFuncAttributeMaxDynamicSharedMemorySize, SMEM_TOTAL);
    cudaFuncSetAttribute(out_kernel,  cudaFuncAttributeMaxDynamicSharedMemorySize, SMEM_TOTAL);

    __nv_bfloat16 *xhi, *xlo, *wahi, *walo, *bwhi, *bwlo, *chi, *clo, *dhi, *dlo;
    cudaGetSymbolAddress((void**)&xhi,  g_xhi);  cudaGetSymbolAddress((void**)&xlo,  g_xlo);
    cudaGetSymbolAddress((void**)&wahi, g_wahi); cudaGetSymbolAddress((void**)&walo, g_walo);
    cudaGetSymbolAddress((void**)&bwhi, g_bwhi); cudaGetSymbolAddress((void**)&bwlo, g_bwlo);
    cudaGetSymbolAddress((void**)&chi,  g_chi);  cudaGetSymbolAddress((void**)&clo,  g_clo);
    cudaGetSymbolAddress((void**)&dhi,  g_dhi);  cudaGetSymbolAddress((void**)&dlo,  g_dlo);

    split_kernel<<<(M_ROWS*DM/4 + 255)/256, 256>>>(x,    xhi,  xlo,  M_ROWS*DM);
    split_kernel<<<(NS*DM/4     + 255)/256, 256>>>(Wa_w, wahi, walo, NS*DM);
    split_kernel<<<(NS*DM/4     + 255)/256, 256>>>(B_w,  bwhi, bwlo, NS*DM);
    split_kernel<<<(DM*NS/4     + 255)/256, 256>>>(C_w,  chi,  clo,  DM*NS);
    split_kernel<<<(DM*DM/4     + 255)/256, 256>>>(D_w,  dhi,  dlo,  DM*DM);

    dim3 blk(256);
    dim3 gproj(M_ROWS / 128, 4);
    proj_kernel<<<gproj, blk, SMEM_TOTAL>>>(Wa_b);

    scan_agg  <<<BATCH * NCHUNK, NS>>>();
    scan_carry<<<BATCH, NS>>>();
    scan_apply<<<BATCH * NCHUNK, NS>>>();

    dim3 gout(M_ROWS / 128, DM / 128);
    out_kernel<<<gout, blk, SMEM_TOTAL>>>(y);
}